// round 8
// baseline (speedup 1.0000x reference)
#include <cuda_runtime.h>
#include <cstdint>

// Perception3D: 7-point stencil, 5 output groups per input channel.
// in : [B=4, C=16, D=64, H=64, W=64] fp32
// out: [B=4, C*G=80, D=64, H=64, W=64] fp32, out channel = c*5+g
//   g=0 ident, g=1 6-neighbor sum, g=2 gx, g=3 gy, g=4 gz (zero-padded shifts)
//
// R8: R6 (256 thr, v8 loads, .wt v8 stores) + per-warp rotation of the
// 5-plane store order to decorrelate the write streams hitting DRAM
// (all planes are exactly 1MB apart; phase-aligned store order means every
// warp stresses the same bank-relation simultaneously).

#define Dz 64
#define Hy 64
#define Wx 64
#define PLANE (Dz * Hy * Wx)
#define ROW   Wx
#define SLAB  (Hy * Wx)
#define W8    (Wx / 8)
#define G 5

__device__ __forceinline__ void ld8(const float* p, float* v) {
    asm("ld.global.nc.v8.f32 {%0,%1,%2,%3,%4,%5,%6,%7}, [%8];"
        : "=f"(v[0]), "=f"(v[1]), "=f"(v[2]), "=f"(v[3]),
          "=f"(v[4]), "=f"(v[5]), "=f"(v[6]), "=f"(v[7])
        : "l"(p));
}

__device__ __forceinline__ void ld8z(const float* p, float* v, bool ok) {
    if (ok) {
        ld8(p, v);
    } else {
#pragma unroll
        for (int i = 0; i < 8; i++) v[i] = 0.f;
    }
}

__device__ __forceinline__ void st8wt(float* p, const float* v) {
    asm volatile("st.global.wt.v8.f32 [%0], {%1,%2,%3,%4,%5,%6,%7,%8};"
        :: "l"(p),
           "f"(v[0]), "f"(v[1]), "f"(v[2]), "f"(v[3]),
           "f"(v[4]), "f"(v[5]), "f"(v[6]), "f"(v[7])
        : "memory");
}

__global__ void __launch_bounds__(256)
perception3d_kernel(const float* __restrict__ in, float* __restrict__ out) {
    // tid over BC * D * H * W8 = 64*64*64*8 = 2,097,152
    unsigned tid = blockIdx.x * blockDim.x + threadIdx.x;

    unsigned w8 = tid & (W8 - 1);          // 0..7
    unsigned h  = (tid >> 3) & (Hy - 1);   // 0..63
    unsigned d  = (tid >> 9) & (Dz - 1);   // 0..63
    unsigned bc = tid >> 15;               // 0..63

    const float* base = in + (size_t)bc * PLANE + (size_t)d * SLAB + (size_t)h * ROW + (size_t)w8 * 8;

    float c[8], xp[8], xm[8], yp[8], ym[8];
    ld8(base, c);
    ld8z(base + SLAB, xp, d + 1 < Dz);
    ld8z(base - SLAB, xm, d >= 1);
    ld8z(base + ROW,  yp, h + 1 < Hy);
    ld8z(base - ROW,  ym, h >= 1);

    float nextv = (w8 + 1 < W8) ? __ldg(base + 8) : 0.f;
    float prevv = (w8 >= 1)     ? __ldg(base - 1) : 0.f;

    float zp[8], zm[8];
#pragma unroll
    for (int i = 0; i < 8; i++) {
        zp[i] = (i < 7) ? c[i + 1] : nextv;
        zm[i] = (i > 0) ? c[i - 1] : prevv;
    }

    float ns[8], gx[8], gy[8], gz[8];
#pragma unroll
    for (int i = 0; i < 8; i++) {
        ns[i] = xp[i] + xm[i] + yp[i] + ym[i] + zp[i] + zm[i];
        gx[i] = xp[i] - xm[i];
        gy[i] = yp[i] - ym[i];
        gz[i] = zp[i] - zm[i];
    }

    unsigned b  = bc >> 4;
    unsigned cc = bc & 15;
    size_t spatial = (size_t)d * SLAB + (size_t)h * ROW + (size_t)w8 * 8;
    float* ob = out + (size_t)b * (16 * G * PLANE) + (size_t)(cc * G) * PLANE + spatial;

    // Per-warp rotation of store order: decorrelate the 5 write streams.
    unsigned rot = (tid >> 5) % G;
    switch (rot) {
    case 0:
        st8wt(ob,             c);
        st8wt(ob + 1 * PLANE, ns);
        st8wt(ob + 2 * PLANE, gx);
        st8wt(ob + 3 * PLANE, gy);
        st8wt(ob + 4 * PLANE, gz);
        break;
    case 1:
        st8wt(ob + 1 * PLANE, ns);
        st8wt(ob + 2 * PLANE, gx);
        st8wt(ob + 3 * PLANE, gy);
        st8wt(ob + 4 * PLANE, gz);
        st8wt(ob,             c);
        break;
    case 2:
        st8wt(ob + 2 * PLANE, gx);
        st8wt(ob + 3 * PLANE, gy);
        st8wt(ob + 4 * PLANE, gz);
        st8wt(ob,             c);
        st8wt(ob + 1 * PLANE, ns);
        break;
    case 3:
        st8wt(ob + 3 * PLANE, gy);
        st8wt(ob + 4 * PLANE, gz);
        st8wt(ob,             c);
        st8wt(ob + 1 * PLANE, ns);
        st8wt(ob + 2 * PLANE, gx);
        break;
    default:
        st8wt(ob + 4 * PLANE, gz);
        st8wt(ob,             c);
        st8wt(ob + 1 * PLANE, ns);
        st8wt(ob + 2 * PLANE, gx);
        st8wt(ob + 3 * PLANE, gy);
        break;
    }
}

extern "C" void kernel_launch(void* const* d_in, const int* in_sizes, int n_in,
                              void* d_out, int out_size) {
    const float* in = (const float*)d_in[0];
    float* out = (float*)d_out;
    // 2,097,152 threads / 256 = 8192 blocks
    perception3d_kernel<<<8192, 256>>>(in, out);
}

// round 9
// speedup vs baseline: 1.0046x; 1.0046x over previous
#include <cuda_runtime.h>
#include <cstdint>

// Perception3D: 7-point stencil, 5 output groups per input channel.
// in : [B=4, C=16, D=64, H=64, W=64] fp32
// out: [B=4, C*G=80, D=64, H=64, W=64] fp32, out channel = c*5+g
//   g=0 ident, g=1 6-neighbor sum, g=2 gx, g=3 gy, g=4 gz (zero-padded shifts)
//
// R9 (final): R6 config (256 thr, v8.f32 loads, .wt v8 stores) with the two
// W-edge scalar loads replaced by warp shuffles — the 8 lanes covering one
// row are consecutive, so s[w-1]/s[w+8] live in neighboring lanes' registers.
// Kernel is at the HBM pure-write roofline (~5.75 TB/s, 335MB mandatory
// writes; reads L2-resident).

#define Dz 64
#define Hy 64
#define Wx 64
#define PLANE (Dz * Hy * Wx)
#define ROW   Wx
#define SLAB  (Hy * Wx)
#define W8    (Wx / 8)
#define G 5

__device__ __forceinline__ void ld8(const float* p, float* v) {
    asm("ld.global.nc.v8.f32 {%0,%1,%2,%3,%4,%5,%6,%7}, [%8];"
        : "=f"(v[0]), "=f"(v[1]), "=f"(v[2]), "=f"(v[3]),
          "=f"(v[4]), "=f"(v[5]), "=f"(v[6]), "=f"(v[7])
        : "l"(p));
}

__device__ __forceinline__ void ld8z(const float* p, float* v, bool ok) {
    if (ok) {
        ld8(p, v);
    } else {
#pragma unroll
        for (int i = 0; i < 8; i++) v[i] = 0.f;
    }
}

__device__ __forceinline__ void st8wt(float* p, const float* v) {
    asm volatile("st.global.wt.v8.f32 [%0], {%1,%2,%3,%4,%5,%6,%7,%8};"
        :: "l"(p),
           "f"(v[0]), "f"(v[1]), "f"(v[2]), "f"(v[3]),
           "f"(v[4]), "f"(v[5]), "f"(v[6]), "f"(v[7])
        : "memory");
}

__global__ void __launch_bounds__(256)
perception3d_kernel(const float* __restrict__ in, float* __restrict__ out) {
    // tid over BC * D * H * W8 = 64*64*64*8 = 2,097,152
    unsigned tid = blockIdx.x * blockDim.x + threadIdx.x;

    unsigned w8 = tid & (W8 - 1);          // 0..7  == lane & 7
    unsigned h  = (tid >> 3) & (Hy - 1);   // 0..63
    unsigned d  = (tid >> 9) & (Dz - 1);   // 0..63
    unsigned bc = tid >> 15;               // 0..63

    const float* base = in + (size_t)bc * PLANE + (size_t)d * SLAB + (size_t)h * ROW + (size_t)w8 * 8;

    float c[8], xp[8], xm[8], yp[8], ym[8];
    ld8(base, c);
    ld8z(base + SLAB, xp, d + 1 < Dz);
    ld8z(base - SLAB, xm, d >= 1);
    ld8z(base + ROW,  yp, h + 1 < Hy);
    ld8z(base - ROW,  ym, h >= 1);

    // W-edge taps via warp shuffle: lanes (lane&7)==w8 are consecutive along w.
    // s[w8*8 + 8] = lane+1's c[0];  s[w8*8 - 1] = lane-1's c[7].
    float nextv = __shfl_down_sync(0xFFFFFFFFu, c[0], 1);
    float prevv = __shfl_up_sync(0xFFFFFFFFu, c[7], 1);
    if (w8 == W8 - 1) nextv = 0.f;
    if (w8 == 0)      prevv = 0.f;

    float zp[8], zm[8];
#pragma unroll
    for (int i = 0; i < 8; i++) {
        zp[i] = (i < 7) ? c[i + 1] : nextv;
        zm[i] = (i > 0) ? c[i - 1] : prevv;
    }

    float ns[8], gx[8], gy[8], gz[8];
#pragma unroll
    for (int i = 0; i < 8; i++) {
        ns[i] = xp[i] + xm[i] + yp[i] + ym[i] + zp[i] + zm[i];
        gx[i] = xp[i] - xm[i];
        gy[i] = yp[i] - ym[i];
        gz[i] = zp[i] - zm[i];
    }

    unsigned b  = bc >> 4;
    unsigned cc = bc & 15;
    size_t spatial = (size_t)d * SLAB + (size_t)h * ROW + (size_t)w8 * 8;
    float* ob = out + (size_t)b * (16 * G * PLANE) + (size_t)(cc * G) * PLANE + spatial;

    st8wt(ob,             c);
    st8wt(ob + 1 * PLANE, ns);
    st8wt(ob + 2 * PLANE, gx);
    st8wt(ob + 3 * PLANE, gy);
    st8wt(ob + 4 * PLANE, gz);
}

extern "C" void kernel_launch(void* const* d_in, const int* in_sizes, int n_in,
                              void* d_out, int out_size) {
    const float* in = (const float*)d_in[0];
    float* out = (float*)d_out;
    // 2,097,152 threads / 256 = 8192 blocks
    perception3d_kernel<<<8192, 256>>>(in, out);
}

// round 10
// speedup vs baseline: 1.0159x; 1.0113x over previous
#include <cuda_runtime.h>
#include <cstdint>

// Perception3D: 7-point stencil, 5 output groups per input channel.
// in : [B=4, C=16, D=64, H=64, W=64] fp32
// out: [B=4, C*G=80, D=64, H=64, W=64] fp32, out channel = c*5+g
//   g=0 ident, g=1 6-neighbor sum, g=2 gx, g=3 gy, g=4 gz (zero-padded shifts)
//
// FINAL (R6 config): fused single kernel, one thread = 8 consecutive floats
// along W; v8.f32 256-bit loads (LDG.E.256) + st.global.wt v8 stores
// (STG.E.256). 256-thread blocks, 8192 CTAs.
//
// Roofline verdict (R1-R9): measured DRAM traffic == the mandatory 335MB
// write footprint (input is L2-resident); all shape/path/order variants pin
// at 5.6-5.8 TB/s DRAM-active (~72% of spec) — the chip's pure-write HBM
// efficiency wall. This config had the best measured end-to-end time.

#define Dz 64
#define Hy 64
#define Wx 64
#define PLANE (Dz * Hy * Wx)
#define ROW   Wx
#define SLAB  (Hy * Wx)
#define W8    (Wx / 8)
#define G 5

__device__ __forceinline__ void ld8(const float* p, float* v) {
    asm("ld.global.nc.v8.f32 {%0,%1,%2,%3,%4,%5,%6,%7}, [%8];"
        : "=f"(v[0]), "=f"(v[1]), "=f"(v[2]), "=f"(v[3]),
          "=f"(v[4]), "=f"(v[5]), "=f"(v[6]), "=f"(v[7])
        : "l"(p));
}

__device__ __forceinline__ void ld8z(const float* p, float* v, bool ok) {
    if (ok) {
        ld8(p, v);
    } else {
#pragma unroll
        for (int i = 0; i < 8; i++) v[i] = 0.f;
    }
}

__device__ __forceinline__ void st8wt(float* p, const float* v) {
    asm volatile("st.global.wt.v8.f32 [%0], {%1,%2,%3,%4,%5,%6,%7,%8};"
        :: "l"(p),
           "f"(v[0]), "f"(v[1]), "f"(v[2]), "f"(v[3]),
           "f"(v[4]), "f"(v[5]), "f"(v[6]), "f"(v[7])
        : "memory");
}

__global__ void __launch_bounds__(256)
perception3d_kernel(const float* __restrict__ in, float* __restrict__ out) {
    // tid over BC * D * H * W8 = 64*64*64*8 = 2,097,152
    unsigned tid = blockIdx.x * blockDim.x + threadIdx.x;

    unsigned w8 = tid & (W8 - 1);          // 0..7
    unsigned h  = (tid >> 3) & (Hy - 1);   // 0..63
    unsigned d  = (tid >> 9) & (Dz - 1);   // 0..63
    unsigned bc = tid >> 15;               // 0..63

    const float* base = in + (size_t)bc * PLANE + (size_t)d * SLAB + (size_t)h * ROW + (size_t)w8 * 8;

    float c[8], xp[8], xm[8], yp[8], ym[8];
    ld8(base, c);
    ld8z(base + SLAB, xp, d + 1 < Dz);
    ld8z(base - SLAB, xm, d >= 1);
    ld8z(base + ROW,  yp, h + 1 < Hy);
    ld8z(base - ROW,  ym, h >= 1);

    float nextv = (w8 + 1 < W8) ? __ldg(base + 8) : 0.f;
    float prevv = (w8 >= 1)     ? __ldg(base - 1) : 0.f;

    float zp[8], zm[8];
#pragma unroll
    for (int i = 0; i < 8; i++) {
        zp[i] = (i < 7) ? c[i + 1] : nextv;
        zm[i] = (i > 0) ? c[i - 1] : prevv;
    }

    float ns[8], gx[8], gy[8], gz[8];
#pragma unroll
    for (int i = 0; i < 8; i++) {
        ns[i] = xp[i] + xm[i] + yp[i] + ym[i] + zp[i] + zm[i];
        gx[i] = xp[i] - xm[i];
        gy[i] = yp[i] - ym[i];
        gz[i] = zp[i] - zm[i];
    }

    unsigned b  = bc >> 4;
    unsigned cc = bc & 15;
    size_t spatial = (size_t)d * SLAB + (size_t)h * ROW + (size_t)w8 * 8;
    float* ob = out + (size_t)b * (16 * G * PLANE) + (size_t)(cc * G) * PLANE + spatial;

    st8wt(ob,             c);
    st8wt(ob + 1 * PLANE, ns);
    st8wt(ob + 2 * PLANE, gx);
    st8wt(ob + 3 * PLANE, gy);
    st8wt(ob + 4 * PLANE, gz);
}

extern "C" void kernel_launch(void* const* d_in, const int* in_sizes, int n_in,
                              void* d_out, int out_size) {
    const float* in = (const float*)d_in[0];
    float* out = (float*)d_out;
    // 2,097,152 threads / 256 = 8192 blocks
    perception3d_kernel<<<8192, 256>>>(in, out);
}